// round 5
// baseline (speedup 1.0000x reference)
#include <cuda_runtime.h>
#include <math_constants.h>
#include <cstdint>

#define LSEQ 2048
#define BATCH 8
#define NROWS (BATCH*LSEQ)
#define K2N 32
#define K1N 16
#define NG 32
#define HIN 20
#define DM 128
#define DH 32
#define KDIM 640   // NG*HIN

// ---------------- device scratch (static, no allocation) ----------------
__device__ float4 g_cpack[NROWS];
__device__ int   g_idx2[NROWS*K2N];
__device__ float g_M[(size_t)NROWS*KDIM];     // layout: [row][h*32+g]
__device__ float g_satt[NROWS];
__device__ float g_catt[NROWS];
__device__ float g_beta[NROWS];
__device__ float g_nodef[NROWS*2];

// ---------------- packed f32x2 helpers (sm_100+ base ISA) ----------------
__device__ __forceinline__ void fma2(uint64_t& d, uint64_t a, uint64_t b) {
    asm("fma.rn.f32x2 %0, %1, %2, %0;" : "+l"(d) : "l"(a), "l"(b));
}
__device__ __forceinline__ uint64_t dup2(float x) {
    uint64_t r; uint32_t u = __float_as_uint(x);
    asm("mov.b64 %0, {%1, %1};" : "=l"(r) : "r"(u));
    return r;
}
__device__ __forceinline__ float2 unpk(uint64_t v) {
    float lo, hi;
    asm("mov.b64 {%0, %1}, %2;" : "=f"(lo), "=f"(hi) : "l"(v));
    return make_float2(lo, hi);
}

// ---------------- kernel 0: pack coords + squared norm ----------------
__global__ void pack_kernel(const float* __restrict__ frame)
{
    int i = blockIdx.x * 256 + threadIdx.x;
    const float* f = frame + (size_t)i * 12;
    float x = f[0], y = f[1], z = f[2];
    g_cpack[i] = make_float4(x, y, z, x*x + y*y + z*z);
}

// ---------------- kernel 1: 32-NN per row, top-4 register cache ----------
__global__ void __launch_bounds__(128) knn_kernel()
{
    __shared__ float d2s[4][LSEQ];
    int warp = threadIdx.x >> 5, lane = threadIdx.x & 31;
    int row  = blockIdx.x * 4 + warp;
    int b = row >> 11, l = row & (LSEQ-1);
    const float4* cb = g_cpack + (size_t)b * LSEQ;
    float4 ci = cb[l];
    float* dw = d2s[warp];

    float v0 = CUDART_INF_F, v1 = CUDART_INF_F, v2 = CUDART_INF_F, v3 = CUDART_INF_F;
    int   p0 = 0x7fffffff,  p1 = 0x7fffffff,  p2 = 0x7fffffff,  p3 = 0x7fffffff;

    #pragma unroll 4
    for (int t = 0; t < LSEQ/32; t++) {
        int m = (t << 5) + lane;
        float4 cm = cb[m];
        float d = ci.w + cm.w - 2.0f*(ci.x*cm.x + ci.y*cm.y + ci.z*cm.z);
        dw[m] = d;
        if (d < v3) {
            if (d < v1) {
                v3 = v2; p3 = p2; v2 = v1; p2 = p1;
                if (d < v0) { v1 = v0; p1 = p0; v0 = d; p0 = m; }
                else        { v1 = d;  p1 = m; }
            } else {
                if (d < v2) { v3 = v2; p3 = p2; v2 = d; p2 = m; }
                else        { v3 = d;  p3 = m; }
            }
        }
    }
    __syncwarp();

    int myidx = 0;
    for (int s = 0; s < K2N; s++) {
        float v = v0; int p = p0;
        #pragma unroll
        for (int off = 16; off > 0; off >>= 1) {
            float ov = __shfl_down_sync(0xffffffffu, v, off);
            int   op = __shfl_down_sync(0xffffffffu, p, off);
            if (ov < v || (ov == v && op < p)) { v = ov; p = op; }
        }
        p = __shfl_sync(0xffffffffu, p, 0);
        if (lane == s) myidx = p;
        if (p0 == p) {
            dw[p] = CUDART_INF_F;
            v0 = v1; p0 = p1; v1 = v2; p1 = p2; v2 = v3; p2 = p3;
            v3 = CUDART_INF_F; p3 = 0x7fffffff;
            if (v0 == CUDART_INF_F) {
                v0 = v1 = v2 = v3 = CUDART_INF_F;
                p0 = p1 = p2 = p3 = 0x7fffffff;
                for (int t = 0; t < LSEQ/32; t++) {
                    int m = (t << 5) + lane;
                    float d = dw[m];
                    if (d < v3) {
                        if (d < v1) {
                            v3 = v2; p3 = p2; v2 = v1; p2 = p1;
                            if (d < v0) { v1 = v0; p1 = p0; v0 = d; p0 = m; }
                            else        { v1 = d;  p1 = m; }
                        } else {
                            if (d < v2) { v3 = v2; p3 = p2; v2 = d; p2 = m; }
                            else        { v3 = d;  p3 = m; }
                        }
                    }
                }
            }
        }
        __syncwarp();
    }
    g_idx2[row*K2N + lane] = myidx;
}

// ---------------- kernel 2: coords1 + gaussians1 + outer product M ----------
__global__ void __launch_bounds__(256) stage1_kernel(
    const float* __restrict__ frame, const float* __restrict__ attr,
    const int* __restrict__ seq,
    const float* __restrict__ gk1_centers, const float* __restrict__ gk1_prec)
{
    __shared__ __align__(8) float attr_s[8][K1N][HIN];
    __shared__ float co_s[8][K1N][7];
    int warp = threadIdx.x >> 5, lane = threadIdx.x & 31;
    int row  = blockIdx.x * 8 + warp;
    int b = row >> 11, l = row & (LSEQ-1);
    const float* fb = frame + (size_t)b * LSEQ * 12;

    if (lane < K1N) {
        int k = lane;
        int j = g_idx2[row*K2N + k];
        float fi[12];
        #pragma unroll
        for (int d = 0; d < 12; d++) fi[d] = fb[l*12+d];
        float cjx = fb[j*12+0], cjy = fb[j*12+1], cjz = fb[j*12+2];
        float zjx = fb[j*12+9], zjy = fb[j*12+10], zjz = fb[j*12+11];
        float dx = cjx - fi[0], dy = cjy - fi[1], dz = cjz - fi[2];
        float dist = sqrtf(dx*dx + dy*dy + dz*dz + 1e-12f);
        float e0 = dx*fi[3] + dy*fi[4] + dz*fi[5];
        float e1 = dx*fi[6] + dy*fi[7] + dz*fi[8];
        float e2 = dx*fi[9] + dy*fi[10] + dz*fi[11];
        float zz  = fi[9]*zjx + fi[10]*zjy + fi[11]*zjz;
        float ddz = (dx*zjx + dy*zjy + dz*zjz) / dist;
        float zdd = (fi[9]*dx + fi[10]*dy + fi[11]*dz) / dist;
        float seqi = (float)seq[b*LSEQ + l];
        float seqj = (float)seq[b*LSEQ + j];
        float idist = fminf(fabsf(seqj - seqi), 8.0f);
        co_s[warp][k][0] = e0;  co_s[warp][k][1] = e1;  co_s[warp][k][2] = e2;
        co_s[warp][k][3] = idist; co_s[warp][k][4] = zz;
        co_s[warp][k][5] = ddz; co_s[warp][k][6] = zdd;
    } else {
        int k = lane - K1N;
        int j = g_idx2[row*K2N + k];
        const float2* ap = (const float2*)(attr + ((size_t)b*LSEQ + j) * HIN);
        float2* dst = (float2*)&attr_s[warp][k][0];
        #pragma unroll
        for (int h = 0; h < HIN/2; h++) dst[h] = ap[h];
    }
    __syncwarp();

    int g = lane;
    float cen[7], pr[49];
    #pragma unroll
    for (int d = 0; d < 7; d++)  cen[d] = gk1_centers[d*NG + g];
    #pragma unroll
    for (int i = 0; i < 49; i++) pr[i]  = gk1_prec[i*NG + g];

    float acc[HIN];
    #pragma unroll
    for (int h = 0; h < HIN; h++) acc[h] = 0.f;

    for (int k = 0; k < K1N; k++) {
        float diff[7];
        #pragma unroll
        for (int d = 0; d < 7; d++) diff[d] = co_s[warp][k][d] - cen[d];
        float s = 0.f;
        #pragma unroll
        for (int c = 0; c < 7; c++) {
            float y = 0.f;
            #pragma unroll
            for (int d = 0; d < 7; d++) y += diff[d] * pr[d*7 + c];
            s += y*y;
        }
        float gv = __expf(-0.5f * s);
        const float2* av = (const float2*)&attr_s[warp][k][0];
        #pragma unroll
        for (int h = 0; h < HIN/2; h++) {
            float2 a = av[h];
            acc[2*h+0] += gv * a.x;
            acc[2*h+1] += gv * a.y;
        }
    }
    float* mp = &g_M[(size_t)row*KDIM + g];
    #pragma unroll
    for (int h = 0; h < HIN; h++) mp[h*NG] = acc[h];
}

// ---------------- kernel 3: 128x128x16 double-buffered FFMA2 GEMM + heads ---
// dynamic smem layout (floats):
//  [0..4223]      As0(16x132) Bs0(16x132)     -- union with filt_s/emb_s
//  [4224..8447]   As1 Bs1
//  filt_s = [0..16895] (128x132), emb_s = [16896..21119] (128x33)
//  embW_s = [21120..25215] (128x32)
#define GE_SMEM_FLOATS 25216
__global__ void __launch_bounds__(256) gemm_epi_kernel(
    const float* __restrict__ opk,  const float* __restrict__ opb,
    const float* __restrict__ embW, const float* __restrict__ embb,
    const float* __restrict__ betaW, const float* __restrict__ betab,
    const float* __restrict__ sattW, const float* __restrict__ sattb,
    const float* __restrict__ cattW, const float* __restrict__ cattb,
    const float* __restrict__ nodefW, const float* __restrict__ nodefb)
{
    extern __shared__ __align__(16) float sm[];
    float* embW_s = sm + 21120;

    int t  = threadIdx.x;
    int ty = t >> 4, tx = t & 15;
    int row0 = blockIdx.x * 128;

    for (int i = t; i < DM*DH; i += 256) embW_s[i] = embW[i];

    int am  = t >> 1;
    int ac0 = (t & 1) * 8;
    const float* Ap = g_M + (size_t)(row0 + am) * KDIM;
    int bk  = t >> 4;
    int bn0 = ((2*t) & 31) * 4;

    float4 aR0, aR1, bR0, bR1;
    aR0 = *(const float4*)(Ap + ac0);
    aR1 = *(const float4*)(Ap + ac0 + 4);
    {
        int k = bk;
        int sr = (k & 31)*HIN + (k >> 5);   // remap: k=h*32+g -> opk row g*20+h
        bR0 = *(const float4*)(opk + sr*DM + bn0);
        bR1 = *(const float4*)(opk + sr*DM + bn0 + 4);
    }
    {
        float* As = sm;  float* Bs = sm + 2112;
        As[(ac0+0)*132+am]=aR0.x; As[(ac0+1)*132+am]=aR0.y;
        As[(ac0+2)*132+am]=aR0.z; As[(ac0+3)*132+am]=aR0.w;
        As[(ac0+4)*132+am]=aR1.x; As[(ac0+5)*132+am]=aR1.y;
        As[(ac0+6)*132+am]=aR1.z; As[(ac0+7)*132+am]=aR1.w;
        *(float4*)&Bs[bk*132+bn0]   = bR0;
        *(float4*)&Bs[bk*132+bn0+4] = bR1;
    }
    __syncthreads();

    uint64_t acc2[8][4];
    #pragma unroll
    for (int i = 0; i < 8; i++)
        #pragma unroll
        for (int j = 0; j < 4; j++) acc2[i][j] = 0ull;

    for (int it = 0; it < KDIM/16; it++) {
        float* Asb = sm + (it & 1) * 4224;
        float* Bsb = Asb + 2112;
        if (it < KDIM/16 - 1) {
            int k0 = (it+1) * 16;
            aR0 = *(const float4*)(Ap + k0 + ac0);
            aR1 = *(const float4*)(Ap + k0 + ac0 + 4);
            int k = k0 + bk;
            int sr = (k & 31)*HIN + (k >> 5);
            bR0 = *(const float4*)(opk + sr*DM + bn0);
            bR1 = *(const float4*)(opk + sr*DM + bn0 + 4);
        }
        #pragma unroll
        for (int kk = 0; kk < 16; kk++) {
            float4 a0 = *(const float4*)&Asb[kk*132 + ty*8];
            float4 a1 = *(const float4*)&Asb[kk*132 + ty*8 + 4];
            ulonglong2 bq0 = *(const ulonglong2*)&Bsb[kk*132 + tx*8];
            ulonglong2 bq1 = *(const ulonglong2*)&Bsb[kk*132 + tx*8 + 4];
            uint64_t bv[4] = {bq0.x, bq0.y, bq1.x, bq1.y};
            float av[8] = {a0.x,a0.y,a0.z,a0.w,a1.x,a1.y,a1.z,a1.w};
            #pragma unroll
            for (int i = 0; i < 8; i++) {
                uint64_t ad = dup2(av[i]);
                #pragma unroll
                for (int j = 0; j < 4; j++) fma2(acc2[i][j], ad, bv[j]);
            }
        }
        if (it < KDIM/16 - 1) {
            float* Asn = sm + ((it+1) & 1) * 4224;
            float* Bsn = Asn + 2112;
            Asn[(ac0+0)*132+am]=aR0.x; Asn[(ac0+1)*132+am]=aR0.y;
            Asn[(ac0+2)*132+am]=aR0.z; Asn[(ac0+3)*132+am]=aR0.w;
            Asn[(ac0+4)*132+am]=aR1.x; Asn[(ac0+5)*132+am]=aR1.y;
            Asn[(ac0+6)*132+am]=aR1.z; Asn[(ac0+7)*132+am]=aR1.w;
            *(float4*)&Bsn[bk*132+bn0]   = bR0;
            *(float4*)&Bsn[bk*132+bn0+4] = bR1;
        }
        __syncthreads();
    }

    // epilogue: relu(filt) into shared union
    float* filt_s = sm;
    #pragma unroll
    for (int i = 0; i < 8; i++)
        #pragma unroll
        for (int j = 0; j < 4; j++) {
            float2 v = unpk(acc2[i][j]);
            int col = tx*8 + 2*j;
            filt_s[(ty*8+i)*132 + col    ] = fmaxf(v.x + opb[col],   0.f);
            filt_s[(ty*8+i)*132 + col + 1] = fmaxf(v.y + opb[col+1], 0.f);
        }
    __syncthreads();

    // emb = relu(filt @ embW + embb)  -- packed f32x2
    float* emb_s = sm + 16896;
    {
        int r  = t >> 1;
        int jb = (t & 1) * 16;
        uint64_t s2[8];
        #pragma unroll
        for (int q = 0; q < 8; q++) {
            float2 bb = make_float2(embb[jb+2*q], embb[jb+2*q+1]);
            s2[q] = *(const uint64_t*)&bb;
        }
        #pragma unroll 4
        for (int c = 0; c < DM; c++) {
            uint64_t fd = dup2(filt_s[r*132 + c]);
            ulonglong2 w0 = *(const ulonglong2*)&embW_s[c*DH + jb];
            ulonglong2 w1 = *(const ulonglong2*)&embW_s[c*DH + jb + 4];
            ulonglong2 w2 = *(const ulonglong2*)&embW_s[c*DH + jb + 8];
            ulonglong2 w3 = *(const ulonglong2*)&embW_s[c*DH + jb + 12];
            fma2(s2[0], fd, w0.x); fma2(s2[1], fd, w0.y);
            fma2(s2[2], fd, w1.x); fma2(s2[3], fd, w1.y);
            fma2(s2[4], fd, w2.x); fma2(s2[5], fd, w2.y);
            fma2(s2[6], fd, w3.x); fma2(s2[7], fd, w3.y);
        }
        #pragma unroll
        for (int q = 0; q < 8; q++) {
            float2 v = unpk(s2[q]);
            emb_s[r*33 + jb + 2*q    ] = fmaxf(v.x, 0.f);
            emb_s[r*33 + jb + 2*q + 1] = fmaxf(v.y, 0.f);
        }
    }
    __syncthreads();

    if (t < 128) {
        int ri = row0 + t;
        float vb = betab[0], vs = sattb[0], vc = cattb[0];
        float n0 = nodefb[0], n1 = nodefb[1];
        #pragma unroll
        for (int j = 0; j < DH; j++) {
            float e = emb_s[t*33 + j];
            vb += e*betaW[j];
            vs += e*sattW[j];
            vc += e*cattW[j];
            n0 += e*nodefW[j*2+0];
            n1 += e*nodefW[j*2+1];
        }
        g_beta[ri]      = fmaxf(vb, 0.f);
        g_satt[ri]      = fmaxf(vs, 0.f);
        g_catt[ri]      = fmaxf(vc, 0.f);
        g_nodef[ri*2+0] = fmaxf(n0, 0.f);
        g_nodef[ri*2+1] = fmaxf(n1, 0.f);
    }
}

// ---------------- kernel 4: stage-2 gaussians (register coeffs) + softmax ---
__global__ void __launch_bounds__(256) stage2_kernel(
    const float* __restrict__ frame, const int* __restrict__ seq,
    const float* __restrict__ gk2_centers, const float* __restrict__ gk2_prec,
    const float* __restrict__ emb2W, const float* __restrict__ emb2b,
    float* __restrict__ out)
{
    int warp = threadIdx.x >> 5, lane = threadIdx.x & 31;
    int row  = blockIdx.x * 8 + warp;
    int b = row >> 11, l = row & (LSEQ-1);
    const float* fb = frame + (size_t)b * LSEQ * 12;

    int j  = g_idx2[row*K2N + lane];
    int jg = b*LSEQ + j;

    float cix = fb[l*12+0], ciy = fb[l*12+1], ciz = fb[l*12+2];
    float zix = fb[l*12+9], ziy = fb[l*12+10], ziz = fb[l*12+11];
    float cjx = fb[j*12+0], cjy = fb[j*12+1], cjz = fb[j*12+2];
    float zjx = fb[j*12+9], zjy = fb[j*12+10], zjz = fb[j*12+11];
    float dx = cjx-cix, dy = cjy-ciy, dz = cjz-ciz;
    float dist = sqrtf(dx*dx + dy*dy + dz*dz + 1e-12f);
    float zz  = zix*zjx + ziy*zjy + ziz*zjz;
    float ddz = (dx*zjx + dy*zjy + dz*zjz) / dist;
    float zdd = (zix*dx + ziy*dy + ziz*dz) / dist;
    float seqi = (float)seq[b*LSEQ+l];
    float seqj = (float)seq[jg];
    float idist = fminf(fabsf(seqj-seqi), 8.0f);
    float x0 = dist, x1 = zz, x2 = ddz, x3 = zdd, x4 = idist;

    float cen[5], pr[25];
    #pragma unroll
    for (int d = 0; d < 5; d++)  cen[d] = gk2_centers[d*NG + lane];
    #pragma unroll
    for (int i = 0; i < 25; i++) pr[i]  = gk2_prec[i*NG + lane];
    float wn = emb2W[lane];

    float gw_mine = 0.f;
    #pragma unroll 4
    for (int k = 0; k < K2N; k++) {
        float y0 = __shfl_sync(0xffffffffu, x0, k);
        float y1 = __shfl_sync(0xffffffffu, x1, k);
        float y2 = __shfl_sync(0xffffffffu, x2, k);
        float y3 = __shfl_sync(0xffffffffu, x3, k);
        float y4 = __shfl_sync(0xffffffffu, x4, k);
        float d0 = y0-cen[0], d1 = y1-cen[1], d2 = y2-cen[2], d3 = y3-cen[3], d4 = y4-cen[4];
        float s = 0.f;
        #pragma unroll
        for (int c = 0; c < 5; c++) {
            float yv = d0*pr[0*5+c] + d1*pr[1*5+c] + d2*pr[2*5+c]
                     + d3*pr[3*5+c] + d4*pr[4*5+c];
            s += yv*yv;
        }
        float e = __expf(-0.5f*s) * wn;
        #pragma unroll
        for (int off = 16; off > 0; off >>= 1)
            e += __shfl_xor_sync(0xffffffffu, e, off);
        if (lane == k) gw_mine = e;
    }
    float gw = fmaxf(gw_mine + emb2b[0], 0.f);

    float e = (lane == 0) ? g_satt[row] : g_catt[jg];
    float logit = g_beta[row] * e;
    float mx = logit;
    #pragma unroll
    for (int off = 16; off > 0; off >>= 1)
        mx = fmaxf(mx, __shfl_xor_sync(0xffffffffu, mx, off));
    float w = gw * __expf(logit - mx);
    float sw = w;
    #pragma unroll
    for (int off = 16; off > 0; off >>= 1)
        sw += __shfl_xor_sync(0xffffffffu, sw, off);
    float a = w / (sw + 1e-6f);
    float o0 = a * g_nodef[jg*2+0];
    float o1 = a * g_nodef[jg*2+1];
    #pragma unroll
    for (int off = 16; off > 0; off >>= 1) {
        o0 += __shfl_xor_sync(0xffffffffu, o0, off);
        o1 += __shfl_xor_sync(0xffffffffu, o1, off);
    }
    if (lane == 0) { out[row*2+0] = o0; out[row*2+1] = o1; }
}

// ---------------- launcher --------------------------------------------------
extern "C" void kernel_launch(void* const* d_in, const int* in_sizes, int n_in,
                              void* d_out, int out_size)
{
    const float* attr        = (const float*)d_in[0];
    const float* frame       = (const float*)d_in[1];
    const int*   seq         = (const int*)  d_in[2];
    const float* gk1_centers = (const float*)d_in[3];
    const float* gk1_prec    = (const float*)d_in[4];
    const float* opk         = (const float*)d_in[5];
    const float* opb         = (const float*)d_in[6];
    const float* embW        = (const float*)d_in[7];
    const float* embb        = (const float*)d_in[8];
    const float* betaW       = (const float*)d_in[9];
    const float* betab       = (const float*)d_in[10];
    const float* sattW       = (const float*)d_in[11];
    const float* sattb       = (const float*)d_in[12];
    const float* cattW       = (const float*)d_in[13];
    const float* cattb       = (const float*)d_in[14];
    const float* nodefW      = (const float*)d_in[15];
    const float* nodefb      = (const float*)d_in[16];
    const float* gk2_centers = (const float*)d_in[17];
    const float* gk2_prec    = (const float*)d_in[18];
    const float* emb2W       = (const float*)d_in[19];
    const float* emb2b       = (const float*)d_in[20];
    float* out = (float*)d_out;

    cudaFuncSetAttribute(gemm_epi_kernel,
                         cudaFuncAttributeMaxDynamicSharedMemorySize,
                         GE_SMEM_FLOATS * 4);

    pack_kernel<<<NROWS/256, 256>>>(frame);
    knn_kernel<<<NROWS/4, 128>>>();
    stage1_kernel<<<NROWS/8, 256>>>(frame, attr, seq, gk1_centers, gk1_prec);
    gemm_epi_kernel<<<NROWS/128, 256, GE_SMEM_FLOATS*4>>>(
        opk, opb, embW, embb, betaW, betab,
        sattW, sattb, cattW, cattb, nodefW, nodefb);
    stage2_kernel<<<NROWS/8, 256>>>(frame, seq, gk2_centers, gk2_prec,
                                    emb2W, emb2b, out);
}

// round 6
// speedup vs baseline: 1.1771x; 1.1771x over previous
#include <cuda_runtime.h>
#include <math_constants.h>
#include <cstdint>

#define LSEQ 2048
#define BATCH 8
#define NROWS (BATCH*LSEQ)
#define K2N 32
#define K1N 16
#define NG 32
#define HIN 20
#define DM 128
#define DH 32
#define KDIM 640   // NG*HIN
#define NKS 40     // KDIM/16

// ---------------- device scratch (static, no allocation) ----------------
__device__ float4 g_cpack[NROWS];
__device__ int   g_idx2[NROWS*K2N];
__device__ float g_M[(size_t)NROWS*KDIM];     // layout: [row][h*32+g]
__device__ float g_satt[NROWS];
__device__ float g_catt[NROWS];
__device__ float g_beta[NROWS];
__device__ float g_nodef[NROWS*2];
// B fragments: [ks][natom(16)][lane(32)] = {bh0,bh1,bl0,bl1}
__device__ uint4 g_Bfrag[NKS*16*32];

// ---------------- helpers ----------------
__device__ __forceinline__ void cvt_split(float2 v, uint32_t& h, uint32_t& l) {
    uint32_t hh;
    asm("cvt.rn.bf16x2.f32 %0, %1, %2;" : "=r"(hh) : "f"(v.y), "f"(v.x));
    float hx = __uint_as_float(hh << 16);
    float hy = __uint_as_float(hh & 0xffff0000u);
    float lx = v.x - hx, ly = v.y - hy;
    uint32_t ll;
    asm("cvt.rn.bf16x2.f32 %0, %1, %2;" : "=r"(ll) : "f"(ly), "f"(lx));
    h = hh; l = ll;
}
__device__ __forceinline__ void hmma(float* d, const uint32_t* a,
                                     uint32_t b0, uint32_t b1) {
    asm("mma.sync.aligned.m16n8k16.row.col.f32.bf16.bf16.f32 "
        "{%0,%1,%2,%3}, {%4,%5,%6,%7}, {%8,%9}, {%0,%1,%2,%3};"
        : "+f"(d[0]), "+f"(d[1]), "+f"(d[2]), "+f"(d[3])
        : "r"(a[0]), "r"(a[1]), "r"(a[2]), "r"(a[3]), "r"(b0), "r"(b1));
}
__device__ __forceinline__ void fma2(uint64_t& d, uint64_t a, uint64_t b) {
    asm("fma.rn.f32x2 %0, %1, %2, %0;" : "+l"(d) : "l"(a), "l"(b));
}
__device__ __forceinline__ uint64_t dup2(float x) {
    uint64_t r; uint32_t u = __float_as_uint(x);
    asm("mov.b64 %0, {%1, %1};" : "=l"(r) : "r"(u));
    return r;
}
__device__ __forceinline__ float2 unpk(uint64_t v) {
    float lo, hi;
    asm("mov.b64 {%0, %1}, %2;" : "=f"(lo), "=f"(hi) : "l"(v));
    return make_float2(lo, hi);
}

// ---------------- kernel 0: pack coords + squared norm ----------------
__global__ void pack_kernel(const float* __restrict__ frame)
{
    int i = blockIdx.x * 256 + threadIdx.x;
    const float* f = frame + (size_t)i * 12;
    float x = f[0], y = f[1], z = f[2];
    g_cpack[i] = make_float4(x, y, z, x*x + y*y + z*z);
}

// ---------------- kernel 0b: build B fragments (split bf16) ----------------
__global__ void bprep_kernel(const float* __restrict__ opk)
{
    int idx = blockIdx.x * 256 + threadIdx.x;   // 20480
    int lane = idx & 31, na = (idx >> 5) & 15, ks = idx >> 9;
    int g = lane >> 2, t = lane & 3;
    int n = na*8 + g;
    int kb = ks*16 + 2*t;
    // logical k = h*32+gg  ->  opk row = gg*HIN + h
    #define OPK_AT(k) opk[(((k) & 31)*HIN + ((k) >> 5))*DM + n]
    float2 p0 = make_float2(OPK_AT(kb),   OPK_AT(kb+1));
    float2 p1 = make_float2(OPK_AT(kb+8), OPK_AT(kb+9));
    #undef OPK_AT
    uint32_t h0,l0,h1,l1;
    cvt_split(p0, h0, l0);
    cvt_split(p1, h1, l1);
    g_Bfrag[idx] = make_uint4(h0, h1, l0, l1);
}

// ---------------- kernel 1: 32-NN per row, top-4 register cache ----------
__global__ void __launch_bounds__(128) knn_kernel()
{
    __shared__ float d2s[4][LSEQ];
    int warp = threadIdx.x >> 5, lane = threadIdx.x & 31;
    int row  = blockIdx.x * 4 + warp;
    int b = row >> 11, l = row & (LSEQ-1);
    const float4* cb = g_cpack + (size_t)b * LSEQ;
    float4 ci = cb[l];
    float* dw = d2s[warp];

    float v0 = CUDART_INF_F, v1 = CUDART_INF_F, v2 = CUDART_INF_F, v3 = CUDART_INF_F;
    int   p0 = 0x7fffffff,  p1 = 0x7fffffff,  p2 = 0x7fffffff,  p3 = 0x7fffffff;

    #pragma unroll 4
    for (int t = 0; t < LSEQ/32; t++) {
        int m = (t << 5) + lane;
        float4 cm = cb[m];
        float d = ci.w + cm.w - 2.0f*(ci.x*cm.x + ci.y*cm.y + ci.z*cm.z);
        dw[m] = d;
        if (d < v3) {
            if (d < v1) {
                v3 = v2; p3 = p2; v2 = v1; p2 = p1;
                if (d < v0) { v1 = v0; p1 = p0; v0 = d; p0 = m; }
                else        { v1 = d;  p1 = m; }
            } else {
                if (d < v2) { v3 = v2; p3 = p2; v2 = d; p2 = m; }
                else        { v3 = d;  p3 = m; }
            }
        }
    }
    __syncwarp();

    int myidx = 0;
    for (int s = 0; s < K2N; s++) {
        float v = v0; int p = p0;
        #pragma unroll
        for (int off = 16; off > 0; off >>= 1) {
            float ov = __shfl_down_sync(0xffffffffu, v, off);
            int   op = __shfl_down_sync(0xffffffffu, p, off);
            if (ov < v || (ov == v && op < p)) { v = ov; p = op; }
        }
        p = __shfl_sync(0xffffffffu, p, 0);
        if (lane == s) myidx = p;
        if (p0 == p) {
            dw[p] = CUDART_INF_F;
            v0 = v1; p0 = p1; v1 = v2; p1 = p2; v2 = v3; p2 = p3;
            v3 = CUDART_INF_F; p3 = 0x7fffffff;
            if (v0 == CUDART_INF_F) {
                v0 = v1 = v2 = v3 = CUDART_INF_F;
                p0 = p1 = p2 = p3 = 0x7fffffff;
                for (int t = 0; t < LSEQ/32; t++) {
                    int m = (t << 5) + lane;
                    float d = dw[m];
                    if (d < v3) {
                        if (d < v1) {
                            v3 = v2; p3 = p2; v2 = v1; p2 = p1;
                            if (d < v0) { v1 = v0; p1 = p0; v0 = d; p0 = m; }
                            else        { v1 = d;  p1 = m; }
                        } else {
                            if (d < v2) { v3 = v2; p3 = p2; v2 = d; p2 = m; }
                            else        { v3 = d;  p3 = m; }
                        }
                    }
                }
            }
        }
        __syncwarp();
    }
    g_idx2[row*K2N + lane] = myidx;
}

// ---------------- kernel 2: coords1 + gaussians1 + outer product M ----------
__global__ void __launch_bounds__(256) stage1_kernel(
    const float* __restrict__ frame, const float* __restrict__ attr,
    const int* __restrict__ seq,
    const float* __restrict__ gk1_centers, const float* __restrict__ gk1_prec)
{
    __shared__ __align__(8) float attr_s[8][K1N][HIN];
    __shared__ float co_s[8][K1N][7];
    int warp = threadIdx.x >> 5, lane = threadIdx.x & 31;
    int row  = blockIdx.x * 8 + warp;
    int b = row >> 11, l = row & (LSEQ-1);
    const float* fb = frame + (size_t)b * LSEQ * 12;

    if (lane < K1N) {
        int k = lane;
        int j = g_idx2[row*K2N + k];
        float fi[12];
        #pragma unroll
        for (int d = 0; d < 12; d++) fi[d] = fb[l*12+d];
        float cjx = fb[j*12+0], cjy = fb[j*12+1], cjz = fb[j*12+2];
        float zjx = fb[j*12+9], zjy = fb[j*12+10], zjz = fb[j*12+11];
        float dx = cjx - fi[0], dy = cjy - fi[1], dz = cjz - fi[2];
        float dist = sqrtf(dx*dx + dy*dy + dz*dz + 1e-12f);
        float e0 = dx*fi[3] + dy*fi[4] + dz*fi[5];
        float e1 = dx*fi[6] + dy*fi[7] + dz*fi[8];
        float e2 = dx*fi[9] + dy*fi[10] + dz*fi[11];
        float zz  = fi[9]*zjx + fi[10]*zjy + fi[11]*zjz;
        float ddz = (dx*zjx + dy*zjy + dz*zjz) / dist;
        float zdd = (fi[9]*dx + fi[10]*dy + fi[11]*dz) / dist;
        float seqi = (float)seq[b*LSEQ + l];
        float seqj = (float)seq[b*LSEQ + j];
        float idist = fminf(fabsf(seqj - seqi), 8.0f);
        co_s[warp][k][0] = e0;  co_s[warp][k][1] = e1;  co_s[warp][k][2] = e2;
        co_s[warp][k][3] = idist; co_s[warp][k][4] = zz;
        co_s[warp][k][5] = ddz; co_s[warp][k][6] = zdd;
    } else {
        int k = lane - K1N;
        int j = g_idx2[row*K2N + k];
        const float2* ap = (const float2*)(attr + ((size_t)b*LSEQ + j) * HIN);
        float2* dst = (float2*)&attr_s[warp][k][0];
        #pragma unroll
        for (int h = 0; h < HIN/2; h++) dst[h] = ap[h];
    }
    __syncwarp();

    int g = lane;
    float cen[7], pr[49];
    #pragma unroll
    for (int d = 0; d < 7; d++)  cen[d] = gk1_centers[d*NG + g];
    #pragma unroll
    for (int i = 0; i < 49; i++) pr[i]  = gk1_prec[i*NG + g];

    float acc[HIN];
    #pragma unroll
    for (int h = 0; h < HIN; h++) acc[h] = 0.f;

    for (int k = 0; k < K1N; k++) {
        float diff[7];
        #pragma unroll
        for (int d = 0; d < 7; d++) diff[d] = co_s[warp][k][d] - cen[d];
        float s = 0.f;
        #pragma unroll
        for (int c = 0; c < 7; c++) {
            float y = 0.f;
            #pragma unroll
            for (int d = 0; d < 7; d++) y += diff[d] * pr[d*7 + c];
            s += y*y;
        }
        float gv = __expf(-0.5f * s);
        const float2* av = (const float2*)&attr_s[warp][k][0];
        #pragma unroll
        for (int h = 0; h < HIN/2; h++) {
            float2 a = av[h];
            acc[2*h+0] += gv * a.x;
            acc[2*h+1] += gv * a.y;
        }
    }
    float* mp = &g_M[(size_t)row*KDIM + g];
    #pragma unroll
    for (int h = 0; h < HIN; h++) mp[h*NG] = acc[h];
}

// ---------------- kernel 3: HMMA split-bf16 GEMM (128x128xK) + fused heads --
// smem (floats):
//  Bbuf: 2 x 512 uint4 = 4096 floats [0..4096)   -- union with filt_s
//  filt_s = [0..16896) (128x132)
//  emb_s  = [16896..21120) (128x33)
//  embW_s = [21120..25216) (128x32)
#define GE_SMEM_FLOATS 25216
__global__ void __launch_bounds__(256) gemm_epi_kernel(
    const float* __restrict__ opb,
    const float* __restrict__ embW, const float* __restrict__ embb,
    const float* __restrict__ betaW, const float* __restrict__ betab,
    const float* __restrict__ sattW, const float* __restrict__ sattb,
    const float* __restrict__ cattW, const float* __restrict__ cattb,
    const float* __restrict__ nodefW, const float* __restrict__ nodefb)
{
    extern __shared__ __align__(16) float sm[];
    uint4* Bbuf   = (uint4*)sm;              // [2][512]
    float* filt_s = sm;
    float* emb_s  = sm + 16896;
    float* embW_s = sm + 21120;

    int t = threadIdx.x, lane = t & 31, wid = t >> 5;
    int wr = wid >> 1, wc = wid & 1;
    int row0 = blockIdx.x * 128;
    int g = lane >> 2, tg = lane & 3;

    for (int i = t; i < DM*DH; i += 256) embW_s[i] = embW[i];

    // A row pointers for this warp's two m-atoms
    const float* A0 = g_M + (size_t)(row0 + wr*32 +      g    ) * KDIM;
    const float* A1 = g_M + (size_t)(row0 + wr*32 +      g + 8) * KDIM;
    const float* A2 = g_M + (size_t)(row0 + wr*32 + 16 + g    ) * KDIM;
    const float* A3 = g_M + (size_t)(row0 + wr*32 + 16 + g + 8) * KDIM;
    int c0 = 2*tg;

    float acc[2][8][4];
    #pragma unroll
    for (int ma = 0; ma < 2; ma++)
        #pragma unroll
        for (int j = 0; j < 8; j++)
            #pragma unroll
            for (int q = 0; q < 4; q++) acc[ma][j][q] = 0.f;

    // initial B copy (ks=0) + initial A load
    {
        uint4 b0 = g_Bfrag[t], b1 = g_Bfrag[256 + t];
        Bbuf[t] = b0; Bbuf[256 + t] = b1;
    }
    float2 ar[8];
    ar[0] = *(const float2*)(A0 + c0);     ar[1] = *(const float2*)(A1 + c0);
    ar[2] = *(const float2*)(A0 + c0 + 8); ar[3] = *(const float2*)(A1 + c0 + 8);
    ar[4] = *(const float2*)(A2 + c0);     ar[5] = *(const float2*)(A3 + c0);
    ar[6] = *(const float2*)(A2 + c0 + 8); ar[7] = *(const float2*)(A3 + c0 + 8);
    __syncthreads();

    for (int ks = 0; ks < NKS; ks++) {
        // convert current A regs -> hi/lo fragments
        uint32_t ah[2][4], al[2][4];
        #pragma unroll
        for (int ma = 0; ma < 2; ma++)
            #pragma unroll
            for (int r = 0; r < 4; r++)
                cvt_split(ar[ma*4 + r], ah[ma][r], al[ma][r]);

        // prefetch next kstep (A regs + B regs)
        uint4 brA, brB;
        if (ks < NKS-1) {
            int kn = (ks+1)*16 + c0;
            ar[0] = *(const float2*)(A0 + kn);     ar[1] = *(const float2*)(A1 + kn);
            ar[2] = *(const float2*)(A0 + kn + 8); ar[3] = *(const float2*)(A1 + kn + 8);
            ar[4] = *(const float2*)(A2 + kn);     ar[5] = *(const float2*)(A3 + kn);
            ar[6] = *(const float2*)(A2 + kn + 8); ar[7] = *(const float2*)(A3 + kn + 8);
            brA = g_Bfrag[(ks+1)*512 + t];
            brB = g_Bfrag[(ks+1)*512 + 256 + t];
        }

        const uint4* Bc = Bbuf + (ks & 1)*512 + (wc*8)*32 + lane;
        #pragma unroll
        for (int j = 0; j < 8; j++) {
            uint4 bb = Bc[j*32];
            #pragma unroll
            for (int ma = 0; ma < 2; ma++) {
                hmma(acc[ma][j], ah[ma], bb.x, bb.y);   // Ah*Bh
                hmma(acc[ma][j], ah[ma], bb.z, bb.w);   // Ah*Bl
                hmma(acc[ma][j], al[ma], bb.x, bb.y);   // Al*Bh
            }
        }

        if (ks < NKS-1) {
            uint4* dst = Bbuf + ((ks+1) & 1)*512;
            dst[t] = brA; dst[256 + t] = brB;
        }
        __syncthreads();
    }

    // epilogue: accumulators -> relu(filt+bias) in shared (Bbuf dead)
    #pragma unroll
    for (int ma = 0; ma < 2; ma++) {
        int r0 = wr*32 + ma*16 + g;
        #pragma unroll
        for (int j = 0; j < 8; j++) {
            int c = wc*64 + j*8 + c0;
            float b0 = opb[c], b1 = opb[c+1];
            filt_s[ r0     *132 + c    ] = fmaxf(acc[ma][j][0] + b0, 0.f);
            filt_s[ r0     *132 + c + 1] = fmaxf(acc[ma][j][1] + b1, 0.f);
            filt_s[(r0+8)  *132 + c    ] = fmaxf(acc[ma][j][2] + b0, 0.f);
            filt_s[(r0+8)  *132 + c + 1] = fmaxf(acc[ma][j][3] + b1, 0.f);
        }
    }
    __syncthreads();

    // emb = relu(filt @ embW + embb)  (packed f32x2)
    {
        int r  = t >> 1;
        int jb = (t & 1) * 16;
        uint64_t s2[8];
        #pragma unroll
        for (int q = 0; q < 8; q++) {
            float2 bb = make_float2(embb[jb+2*q], embb[jb+2*q+1]);
            s2[q] = *(const uint64_t*)&bb;
        }
        #pragma unroll 4
        for (int c = 0; c < DM; c++) {
            uint64_t fd = dup2(filt_s[r*132 + c]);
            ulonglong2 w0 = *(const ulonglong2*)&embW_s[c*DH + jb];
            ulonglong2 w1 = *(const ulonglong2*)&embW_s[c*DH + jb + 4];
            ulonglong2 w2 = *(const ulonglong2*)&embW_s[c*DH + jb + 8];
            ulonglong2 w3 = *(const ulonglong2*)&embW_s[c*DH + jb + 12];
            fma2(s2[0], fd, w0.x); fma2(s2[1], fd, w0.y);
            fma2(s2[2], fd, w1.x); fma2(s2[3], fd, w1.y);
            fma2(s2[4], fd, w2.x); fma2(s2[5], fd, w2.y);
            fma2(s2[6], fd, w3.x); fma2(s2[7], fd, w3.y);
        }
        #pragma unroll
        for (int q = 0; q < 8; q++) {
            float2 v = unpk(s2[q]);
            emb_s[r*33 + jb + 2*q    ] = fmaxf(v.x, 0.f);
            emb_s[r*33 + jb + 2*q + 1] = fmaxf(v.y, 0.f);
        }
    }
    __syncthreads();

    if (t < 128) {
        int ri = row0 + t;
        float vb = betab[0], vs = sattb[0], vc = cattb[0];
        float n0 = nodefb[0], n1 = nodefb[1];
        #pragma unroll
        for (int j = 0; j < DH; j++) {
            float e = emb_s[t*33 + j];
            vb += e*betaW[j];
            vs += e*sattW[j];
            vc += e*cattW[j];
            n0 += e*nodefW[j*2+0];
            n1 += e*nodefW[j*2+1];
        }
        g_beta[ri]      = fmaxf(vb, 0.f);
        g_satt[ri]      = fmaxf(vs, 0.f);
        g_catt[ri]      = fmaxf(vc, 0.f);
        g_nodef[ri*2+0] = fmaxf(n0, 0.f);
        g_nodef[ri*2+1] = fmaxf(n1, 0.f);
    }
}

// ---------------- kernel 4: stage-2 gaussians (register coeffs) + softmax ---
__global__ void __launch_bounds__(256) stage2_kernel(
    const float* __restrict__ frame, const int* __restrict__ seq,
    const float* __restrict__ gk2_centers, const float* __restrict__ gk2_prec,
    const float* __restrict__ emb2W, const float* __restrict__ emb2b,
    float* __restrict__ out)
{
    int warp = threadIdx.x >> 5, lane = threadIdx.x & 31;
    int row  = blockIdx.x * 8 + warp;
    int b = row >> 11, l = row & (LSEQ-1);
    const float* fb = frame + (size_t)b * LSEQ * 12;

    int j  = g_idx2[row*K2N + lane];
    int jg = b*LSEQ + j;

    float cix = fb[l*12+0], ciy = fb[l*12+1], ciz = fb[l*12+2];
    float zix = fb[l*12+9], ziy = fb[l*12+10], ziz = fb[l*12+11];
    float cjx = fb[j*12+0], cjy = fb[j*12+1], cjz = fb[j*12+2];
    float zjx = fb[j*12+9], zjy = fb[j*12+10], zjz = fb[j*12+11];
    float dx = cjx-cix, dy = cjy-ciy, dz = cjz-ciz;
    float dist = sqrtf(dx*dx + dy*dy + dz*dz + 1e-12f);
    float zz  = zix*zjx + ziy*zjy + ziz*zjz;
    float ddz = (dx*zjx + dy*zjy + dz*zjz) / dist;
    float zdd = (zix*dx + ziy*dy + ziz*dz) / dist;
    float seqi = (float)seq[b*LSEQ+l];
    float seqj = (float)seq[jg];
    float idist = fminf(fabsf(seqj-seqi), 8.0f);
    float x0 = dist, x1 = zz, x2 = ddz, x3 = zdd, x4 = idist;

    float cen[5], pr[25];
    #pragma unroll
    for (int d = 0; d < 5; d++)  cen[d] = gk2_centers[d*NG + lane];
    #pragma unroll
    for (int i = 0; i < 25; i++) pr[i]  = gk2_prec[i*NG + lane];
    float wn = emb2W[lane];

    float gw_mine = 0.f;
    #pragma unroll 4
    for (int k = 0; k < K2N; k++) {
        float y0 = __shfl_sync(0xffffffffu, x0, k);
        float y1 = __shfl_sync(0xffffffffu, x1, k);
        float y2 = __shfl_sync(0xffffffffu, x2, k);
        float y3 = __shfl_sync(0xffffffffu, x3, k);
        float y4 = __shfl_sync(0xffffffffu, x4, k);
        float d0 = y0-cen[0], d1 = y1-cen[1], d2 = y2-cen[2], d3 = y3-cen[3], d4 = y4-cen[4];
        float s = 0.f;
        #pragma unroll
        for (int c = 0; c < 5; c++) {
            float yv = d0*pr[0*5+c] + d1*pr[1*5+c] + d2*pr[2*5+c]
                     + d3*pr[3*5+c] + d4*pr[4*5+c];
            s += yv*yv;
        }
        float e = __expf(-0.5f*s) * wn;
        #pragma unroll
        for (int off = 16; off > 0; off >>= 1)
            e += __shfl_xor_sync(0xffffffffu, e, off);
        if (lane == k) gw_mine = e;
    }
    float gw = fmaxf(gw_mine + emb2b[0], 0.f);

    float e = (lane == 0) ? g_satt[row] : g_catt[jg];
    float logit = g_beta[row] * e;
    float mx = logit;
    #pragma unroll
    for (int off = 16; off > 0; off >>= 1)
        mx = fmaxf(mx, __shfl_xor_sync(0xffffffffu, mx, off));
    float w = gw * __expf(logit - mx);
    float sw = w;
    #pragma unroll
    for (int off = 16; off > 0; off >>= 1)
        sw += __shfl_xor_sync(0xffffffffu, sw, off);
    float a = w / (sw + 1e-6f);
    float o0 = a * g_nodef[jg*2+0];
    float o1 = a * g_nodef[jg*2+1];
    #pragma unroll
    for (int off = 16; off > 0; off >>= 1) {
        o0 += __shfl_xor_sync(0xffffffffu, o0, off);
        o1 += __shfl_xor_sync(0xffffffffu, o1, off);
    }
    if (lane == 0) { out[row*2+0] = o0; out[row*2+1] = o1; }
}

// ---------------- launcher --------------------------------------------------
extern "C" void kernel_launch(void* const* d_in, const int* in_sizes, int n_in,
                              void* d_out, int out_size)
{
    const float* attr        = (const float*)d_in[0];
    const float* frame       = (const float*)d_in[1];
    const int*   seq         = (const int*)  d_in[2];
    const float* gk1_centers = (const float*)d_in[3];
    const float* gk1_prec    = (const float*)d_in[4];
    const float* opk         = (const float*)d_in[5];
    const float* opb         = (const float*)d_in[6];
    const float* embW        = (const float*)d_in[7];
    const float* embb        = (const float*)d_in[8];
    const float* betaW       = (const float*)d_in[9];
    const float* betab       = (const float*)d_in[10];
    const float* sattW       = (const float*)d_in[11];
    const float* sattb       = (const float*)d_in[12];
    const float* cattW       = (const float*)d_in[13];
    const float* cattb       = (const float*)d_in[14];
    const float* nodefW      = (const float*)d_in[15];
    const float* nodefb      = (const float*)d_in[16];
    const float* gk2_centers = (const float*)d_in[17];
    const float* gk2_prec    = (const float*)d_in[18];
    const float* emb2W       = (const float*)d_in[19];
    const float* emb2b       = (const float*)d_in[20];
    float* out = (float*)d_out;

    cudaFuncSetAttribute(gemm_epi_kernel,
                         cudaFuncAttributeMaxDynamicSharedMemorySize,
                         GE_SMEM_FLOATS * 4);

    pack_kernel<<<NROWS/256, 256>>>(frame);
    bprep_kernel<<<80, 256>>>(opk);
    knn_kernel<<<NROWS/4, 128>>>();
    stage1_kernel<<<NROWS/8, 256>>>(frame, attr, seq, gk1_centers, gk1_prec);
    gemm_epi_kernel<<<NROWS/128, 256, GE_SMEM_FLOATS*4>>>(
        opb, embW, embb, betaW, betab,
        sattW, sattb, cattW, cattb, nodefW, nodefb);
    stage2_kernel<<<NROWS/8, 256>>>(frame, seq, gk2_centers, gk2_prec,
                                    emb2W, emb2b, out);
}

// round 7
// speedup vs baseline: 1.2893x; 1.0953x over previous
#include <cuda_runtime.h>
#include <math_constants.h>
#include <cstdint>

#define LSEQ 2048
#define BATCH 8
#define NROWS (BATCH*LSEQ)
#define K2N 32
#define K1N 16
#define NG 32
#define HIN 20
#define DM 128
#define DH 32
#define KDIM 640   // NG*HIN
#define NKS 40     // KDIM/16

// ---------------- device scratch (static, no allocation) ----------------
__device__ float4 g_cpack[NROWS];
__device__ int   g_idx2[NROWS*K2N];
__device__ float g_M[(size_t)NROWS*KDIM];     // layout: [row][h*32+g]
__device__ float g_satt[NROWS];
__device__ float g_catt[NROWS];
__device__ float g_beta[NROWS];
__device__ float g_nodef[NROWS*2];
// B fragments: [ks][natom(16)][lane(32)] = {bh0,bh1,bl0,bl1}
__device__ uint4 g_Bfrag[NKS*16*32];
// stage1 quadratic-form coeffs: 18 pairs x 32 gaussians x 2
__device__ float g_Q[18*32*2];

// ---------------- helpers ----------------
__device__ __forceinline__ void cvt_split(float2 v, uint32_t& h, uint32_t& l) {
    uint32_t hh;
    asm("cvt.rn.bf16x2.f32 %0, %1, %2;" : "=r"(hh) : "f"(v.y), "f"(v.x));
    float hx = __uint_as_float(hh << 16);
    float hy = __uint_as_float(hh & 0xffff0000u);
    float lx = v.x - hx, ly = v.y - hy;
    uint32_t ll;
    asm("cvt.rn.bf16x2.f32 %0, %1, %2;" : "=r"(ll) : "f"(ly), "f"(lx));
    h = hh; l = ll;
}
__device__ __forceinline__ void hmma(float* d, const uint32_t* a,
                                     uint32_t b0, uint32_t b1) {
    asm("mma.sync.aligned.m16n8k16.row.col.f32.bf16.bf16.f32 "
        "{%0,%1,%2,%3}, {%4,%5,%6,%7}, {%8,%9}, {%0,%1,%2,%3};"
        : "+f"(d[0]), "+f"(d[1]), "+f"(d[2]), "+f"(d[3])
        : "r"(a[0]), "r"(a[1]), "r"(a[2]), "r"(a[3]), "r"(b0), "r"(b1));
}
__device__ __forceinline__ void fma2(uint64_t& d, uint64_t a, uint64_t b) {
    asm("fma.rn.f32x2 %0, %1, %2, %0;" : "+l"(d) : "l"(a), "l"(b));
}
__device__ __forceinline__ uint64_t dup2(float x) {
    uint64_t r; uint32_t u = __float_as_uint(x);
    asm("mov.b64 %0, {%1, %1};" : "=l"(r) : "r"(u));
    return r;
}
__device__ __forceinline__ float2 unpk(uint64_t v) {
    float lo, hi;
    asm("mov.b64 {%0, %1}, %2;" : "=f"(lo), "=f"(hi) : "l"(v));
    return make_float2(lo, hi);
}

// ---------------- kernel 0: pack coords + squared norm ----------------
__global__ void pack_kernel(const float* __restrict__ frame)
{
    int i = blockIdx.x * 256 + threadIdx.x;
    const float* f = frame + (size_t)i * 12;
    float x = f[0], y = f[1], z = f[2];
    g_cpack[i] = make_float4(x, y, z, x*x + y*y + z*z);
}

// ---------------- kernel 0b: build B fragments (split bf16) ----------------
__global__ void bprep_kernel(const float* __restrict__ opk)
{
    int idx = blockIdx.x * 256 + threadIdx.x;   // 20480
    int lane = idx & 31, na = (idx >> 5) & 15, ks = idx >> 9;
    int g = lane >> 2, t = lane & 3;
    int n = na*8 + g;
    int kb = ks*16 + 2*t;
    #define OPK_AT(k) opk[(((k) & 31)*HIN + ((k) >> 5))*DM + n]
    float2 p0 = make_float2(OPK_AT(kb),   OPK_AT(kb+1));
    float2 p1 = make_float2(OPK_AT(kb+8), OPK_AT(kb+9));
    #undef OPK_AT
    uint32_t h0,l0,h1,l1;
    cvt_split(p0, h0, l0);
    cvt_split(p1, h1, l1);
    g_Bfrag[idx] = make_uint4(h0, h1, l0, l1);
}

// ---------------- kernel 0c: fold gk1 prec/centers into quadratic coeffs ----
// s = diff^T (P P^T) diff  ->  x^T A x + b^T x + c
// feature order: f[0..6]=x_d, f[7..34]=x_d*x_e (d<=e row-major), f[35]=1
__global__ void qprep_kernel(const float* __restrict__ gk1_centers,
                             const float* __restrict__ gk1_prec)
{
    int g = threadIdx.x;
    float P[7][7], c[7];
    #pragma unroll
    for (int d = 0; d < 7; d++) {
        c[d] = gk1_centers[d*NG + g];
        #pragma unroll
        for (int k = 0; k < 7; k++) P[d][k] = gk1_prec[(d*7+k)*NG + g];
    }
    float A[7][7];
    #pragma unroll
    for (int d = 0; d < 7; d++)
        #pragma unroll
        for (int e = 0; e < 7; e++) {
            float s = 0.f;
            #pragma unroll
            for (int k = 0; k < 7; k++) s += P[d][k]*P[e][k];
            A[d][e] = s;
        }
    float coeff[36];
    #pragma unroll
    for (int d = 0; d < 7; d++) {
        float s = 0.f;
        #pragma unroll
        for (int e = 0; e < 7; e++) s += A[d][e]*c[e];
        coeff[d] = -2.f*s;
    }
    int i = 7;
    #pragma unroll
    for (int d = 0; d < 7; d++)
        #pragma unroll
        for (int e = 0; e < 7; e++)
            if (e >= d) coeff[i++] = A[d][e]*((d==e)?1.f:2.f);
    float cc = 0.f;
    #pragma unroll
    for (int d = 0; d < 7; d++)
        #pragma unroll
        for (int e = 0; e < 7; e++) cc += c[d]*A[d][e]*c[e];
    coeff[35] = cc;
    #pragma unroll
    for (int p = 0; p < 18; p++) {
        g_Q[(p*32+g)*2 + 0] = coeff[2*p];
        g_Q[(p*32+g)*2 + 1] = coeff[2*p+1];
    }
}

// ---------------- kernel 1: 32-NN per row, top-4 cache + REDUX argmin ------
__global__ void __launch_bounds__(128) knn_kernel()
{
    __shared__ float d2s[4][LSEQ];
    int warp = threadIdx.x >> 5, lane = threadIdx.x & 31;
    int row  = blockIdx.x * 4 + warp;
    int b = row >> 11, l = row & (LSEQ-1);
    const float4* cb = g_cpack + (size_t)b * LSEQ;
    float4 ci = cb[l];
    float* dw = d2s[warp];

    float v0 = CUDART_INF_F, v1 = CUDART_INF_F, v2 = CUDART_INF_F, v3 = CUDART_INF_F;
    int   p0 = 0x7fffffff,  p1 = 0x7fffffff,  p2 = 0x7fffffff,  p3 = 0x7fffffff;

    #pragma unroll 4
    for (int t = 0; t < LSEQ/32; t++) {
        int m = (t << 5) + lane;
        float4 cm = cb[m];
        float d = ci.w + cm.w - 2.0f*(ci.x*cm.x + ci.y*cm.y + ci.z*cm.z);
        dw[m] = d;
        if (d < v3) {
            if (d < v1) {
                v3 = v2; p3 = p2; v2 = v1; p2 = p1;
                if (d < v0) { v1 = v0; p1 = p0; v0 = d; p0 = m; }
                else        { v1 = d;  p1 = m; }
            } else {
                if (d < v2) { v3 = v2; p3 = p2; v2 = d; p2 = m; }
                else        { v3 = d;  p3 = m; }
            }
        }
    }
    __syncwarp();

    int myidx = 0;
    for (int s = 0; s < K2N; s++) {
        uint32_t bits = __float_as_uint(v0);           // d2 >= 0: bit order = value order
        uint32_t mn   = __reduce_min_sync(0xffffffffu, bits);
        uint32_t ball = __ballot_sync(0xffffffffu, bits == mn);
        int p;
        if (__popc(ball) == 1) {
            p = __shfl_sync(0xffffffffu, p0, __ffs(ball)-1);
        } else {                                       // exact tie: min global index
            int cand = (bits == mn) ? p0 : 0x7fffffff;
            #pragma unroll
            for (int off = 16; off > 0; off >>= 1)
                cand = min(cand, __shfl_down_sync(0xffffffffu, cand, off));
            p = __shfl_sync(0xffffffffu, cand, 0);
        }
        if (lane == s) myidx = p;
        if (p0 == p) {
            dw[p] = CUDART_INF_F;
            v0 = v1; p0 = p1; v1 = v2; p1 = p2; v2 = v3; p2 = p3;
            v3 = CUDART_INF_F; p3 = 0x7fffffff;
            if (v0 == CUDART_INF_F) {                  // rare refill
                v0 = v1 = v2 = v3 = CUDART_INF_F;
                p0 = p1 = p2 = p3 = 0x7fffffff;
                for (int t = 0; t < LSEQ/32; t++) {
                    int m = (t << 5) + lane;
                    float d = dw[m];
                    if (d < v3) {
                        if (d < v1) {
                            v3 = v2; p3 = p2; v2 = v1; p2 = p1;
                            if (d < v0) { v1 = v0; p1 = p0; v0 = d; p0 = m; }
                            else        { v1 = d;  p1 = m; }
                        } else {
                            if (d < v2) { v3 = v2; p3 = p2; v2 = d; p2 = m; }
                            else        { v3 = d;  p3 = m; }
                        }
                    }
                }
            }
        }
        __syncwarp();
    }
    g_idx2[row*K2N + lane] = myidx;
}

// ---------------- kernel 2: coords1 features + packed gaussian dot ----------
__global__ void __launch_bounds__(256) stage1_kernel(
    const float* __restrict__ frame, const float* __restrict__ attr,
    const int* __restrict__ seq)
{
    __shared__ __align__(16) float attr_s[8][K1N][HIN];
    __shared__ __align__(16) float feat_s[8][K1N][36];
    int warp = threadIdx.x >> 5, lane = threadIdx.x & 31;
    int row  = blockIdx.x * 8 + warp;
    int b = row >> 11, l = row & (LSEQ-1);
    const float* fb = frame + (size_t)b * LSEQ * 12;

    if (lane < K1N) {
        int k = lane;
        int j = g_idx2[row*K2N + k];
        float fi[12];
        #pragma unroll
        for (int d = 0; d < 12; d++) fi[d] = fb[l*12+d];
        float cjx = fb[j*12+0], cjy = fb[j*12+1], cjz = fb[j*12+2];
        float zjx = fb[j*12+9], zjy = fb[j*12+10], zjz = fb[j*12+11];
        float dx = cjx - fi[0], dy = cjy - fi[1], dz = cjz - fi[2];
        float dist = sqrtf(dx*dx + dy*dy + dz*dz + 1e-12f);
        float x[7];
        x[0] = dx*fi[3] + dy*fi[4] + dz*fi[5];
        x[1] = dx*fi[6] + dy*fi[7] + dz*fi[8];
        x[2] = dx*fi[9] + dy*fi[10] + dz*fi[11];
        float seqi = (float)seq[b*LSEQ + l];
        float seqj = (float)seq[b*LSEQ + j];
        x[3] = fminf(fabsf(seqj - seqi), 8.0f);
        x[4] = fi[9]*zjx + fi[10]*zjy + fi[11]*zjz;
        x[5] = (dx*zjx + dy*zjy + dz*zjz) / dist;
        x[6] = (fi[9]*dx + fi[10]*dy + fi[11]*dz) / dist;
        float fv[36];
        #pragma unroll
        for (int d = 0; d < 7; d++) fv[d] = x[d];
        int i = 7;
        #pragma unroll
        for (int d = 0; d < 7; d++)
            #pragma unroll
            for (int e = 0; e < 7; e++)
                if (e >= d) fv[i++] = x[d]*x[e];
        fv[35] = 1.0f;
        float4* fd = (float4*)&feat_s[warp][k][0];
        #pragma unroll
        for (int q = 0; q < 9; q++)
            fd[q] = make_float4(fv[4*q], fv[4*q+1], fv[4*q+2], fv[4*q+3]);
    } else {
        int k = lane - K1N;
        int j = g_idx2[row*K2N + k];
        const float2* ap = (const float2*)(attr + ((size_t)b*LSEQ + j) * HIN);
        float2* dst = (float2*)&attr_s[warp][k][0];
        #pragma unroll
        for (int h = 0; h < HIN/2; h++) dst[h] = ap[h];
    }
    __syncwarp();

    int g = lane;
    uint64_t cq[18];
    #pragma unroll
    for (int p = 0; p < 18; p++)
        cq[p] = *(const uint64_t*)&g_Q[(p*32+g)*2];

    uint64_t acc2[10];
    #pragma unroll
    for (int h = 0; h < 10; h++) acc2[h] = 0ull;

    for (int k = 0; k < K1N; k++) {
        const ulonglong2* fp = (const ulonglong2*)&feat_s[warp][k][0];
        uint64_t sa = 0ull, sb = 0ull, sc = 0ull;
        #pragma unroll
        for (int q = 0; q < 9; q++) {
            ulonglong2 f = fp[q];
            if (q % 3 == 0)      { fma2(sa, cq[2*q], f.x); fma2(sb, cq[2*q+1], f.y); }
            else if (q % 3 == 1) { fma2(sc, cq[2*q], f.x); fma2(sa, cq[2*q+1], f.y); }
            else                 { fma2(sb, cq[2*q], f.x); fma2(sc, cq[2*q+1], f.y); }
        }
        float2 va = unpk(sa), vb = unpk(sb), vc = unpk(sc);
        float s = ((va.x + va.y) + (vb.x + vb.y)) + (vc.x + vc.y);
        float gv = __expf(-0.5f * s);
        uint64_t gd = dup2(gv);
        const ulonglong2* ap = (const ulonglong2*)&attr_s[warp][k][0];
        #pragma unroll
        for (int q = 0; q < 5; q++) {
            ulonglong2 a = ap[q];
            fma2(acc2[2*q],   gd, a.x);
            fma2(acc2[2*q+1], gd, a.y);
        }
    }
    float* mp = &g_M[(size_t)row*KDIM + g];
    #pragma unroll
    for (int p = 0; p < 10; p++) {
        float2 v = unpk(acc2[p]);
        mp[(2*p  )*NG] = v.x;
        mp[(2*p+1)*NG] = v.y;
    }
}

// ---------------- kernel 3: HMMA split-bf16 GEMM (128x128xK) + fused heads --
#define GE_SMEM_FLOATS 25216
__global__ void __launch_bounds__(256) gemm_epi_kernel(
    const float* __restrict__ opb,
    const float* __restrict__ embW, const float* __restrict__ embb,
    const float* __restrict__ betaW, const float* __restrict__ betab,
    const float* __restrict__ sattW, const float* __restrict__ sattb,
    const float* __restrict__ cattW, const float* __restrict__ cattb,
    const float* __restrict__ nodefW, const float* __restrict__ nodefb)
{
    extern __shared__ __align__(16) float sm[];
    uint4* Bbuf   = (uint4*)sm;              // [2][512]
    float* filt_s = sm;
    float* emb_s  = sm + 16896;
    float* embW_s = sm + 21120;

    int t = threadIdx.x, lane = t & 31, wid = t >> 5;
    int wr = wid >> 1, wc = wid & 1;
    int row0 = blockIdx.x * 128;
    int g = lane >> 2, tg = lane & 3;

    for (int i = t; i < DM*DH; i += 256) embW_s[i] = embW[i];

    const float* A0 = g_M + (size_t)(row0 + wr*32 +      g    ) * KDIM;
    const float* A1 = g_M + (size_t)(row0 + wr*32 +      g + 8) * KDIM;
    const float* A2 = g_M + (size_t)(row0 + wr*32 + 16 + g    ) * KDIM;
    const float* A3 = g_M + (size_t)(row0 + wr*32 + 16 + g + 8) * KDIM;
    int c0 = 2*tg;

    float acc[2][8][4];
    #pragma unroll
    for (int ma = 0; ma < 2; ma++)
        #pragma unroll
        for (int j = 0; j < 8; j++)
            #pragma unroll
            for (int q = 0; q < 4; q++) acc[ma][j][q] = 0.f;

    {
        uint4 b0 = g_Bfrag[t], b1 = g_Bfrag[256 + t];
        Bbuf[t] = b0; Bbuf[256 + t] = b1;
    }
    float2 ar[8];
    ar[0] = *(const float2*)(A0 + c0);     ar[1] = *(const float2*)(A1 + c0);
    ar[2] = *(const float2*)(A0 + c0 + 8); ar[3] = *(const float2*)(A1 + c0 + 8);
    ar[4] = *(const float2*)(A2 + c0);     ar[5] = *(const float2*)(A3 + c0);
    ar[6] = *(const float2*)(A2 + c0 + 8); ar[7] = *(const float2*)(A3 + c0 + 8);
    __syncthreads();

    for (int ks = 0; ks < NKS; ks++) {
        uint32_t ah[2][4], al[2][4];
        #pragma unroll
        for (int ma = 0; ma < 2; ma++)
            #pragma unroll
            for (int r = 0; r < 4; r++)
                cvt_split(ar[ma*4 + r], ah[ma][r], al[ma][r]);

        uint4 brA, brB;
        if (ks < NKS-1) {
            int kn = (ks+1)*16 + c0;
            ar[0] = *(const float2*)(A0 + kn);     ar[1] = *(const float2*)(A1 + kn);
            ar[2] = *(const float2*)(A0 + kn + 8); ar[3] = *(const float2*)(A1 + kn + 8);
            ar[4] = *(const float2*)(A2 + kn);     ar[5] = *(const float2*)(A3 + kn);
            ar[6] = *(const float2*)(A2 + kn + 8); ar[7] = *(const float2*)(A3 + kn + 8);
            brA = g_Bfrag[(ks+1)*512 + t];
            brB = g_Bfrag[(ks+1)*512 + 256 + t];
        }

        const uint4* Bc = Bbuf + (ks & 1)*512 + (wc*8)*32 + lane;
        #pragma unroll
        for (int j = 0; j < 8; j++) {
            uint4 bb = Bc[j*32];
            #pragma unroll
            for (int ma = 0; ma < 2; ma++) {
                hmma(acc[ma][j], ah[ma], bb.x, bb.y);
                hmma(acc[ma][j], ah[ma], bb.z, bb.w);
                hmma(acc[ma][j], al[ma], bb.x, bb.y);
            }
        }

        if (ks < NKS-1) {
            uint4* dst = Bbuf + ((ks+1) & 1)*512;
            dst[t] = brA; dst[256 + t] = brB;
        }
        __syncthreads();
    }

    #pragma unroll
    for (int ma = 0; ma < 2; ma++) {
        int r0 = wr*32 + ma*16 + g;
        #pragma unroll
        for (int j = 0; j < 8; j++) {
            int c = wc*64 + j*8 + c0;
            float b0 = opb[c], b1 = opb[c+1];
            filt_s[ r0     *132 + c    ] = fmaxf(acc[ma][j][0] + b0, 0.f);
            filt_s[ r0     *132 + c + 1] = fmaxf(acc[ma][j][1] + b1, 0.f);
            filt_s[(r0+8)  *132 + c    ] = fmaxf(acc[ma][j][2] + b0, 0.f);
            filt_s[(r0+8)  *132 + c + 1] = fmaxf(acc[ma][j][3] + b1, 0.f);
        }
    }
    __syncthreads();

    {
        int r  = t >> 1;
        int jb = (t & 1) * 16;
        uint64_t s2[8];
        #pragma unroll
        for (int q = 0; q < 8; q++) {
            float2 bb = make_float2(embb[jb+2*q], embb[jb+2*q+1]);
            s2[q] = *(const uint64_t*)&bb;
        }
        #pragma unroll 4
        for (int c = 0; c < DM; c++) {
            uint64_t fd = dup2(filt_s[r*132 + c]);
            ulonglong2 w0 = *(const ulonglong2*)&embW_s[c*DH + jb];
            ulonglong2 w1 = *(const ulonglong2*)&embW_s[c*DH + jb + 4];
            ulonglong2 w2 = *(const ulonglong2*)&embW_s[c*DH + jb + 8];
            ulonglong2 w3 = *(const ulonglong2*)&embW_s[c*DH + jb + 12];
            fma2(s2[0], fd, w0.x); fma2(s2[1], fd, w0.y);
            fma2(s2[2], fd, w1.x); fma2(s2[3], fd, w1.y);
            fma2(s2[4], fd, w2.x); fma2(s2[5], fd, w2.y);
            fma2(s2[6], fd, w3.x); fma2(s2[7], fd, w3.y);
        }
        #pragma unroll
        for (int q = 0; q < 8; q++) {
            float2 v = unpk(s2[q]);
            emb_s[r*33 + jb + 2*q    ] = fmaxf(v.x, 0.f);
            emb_s[r*33 + jb + 2*q + 1] = fmaxf(v.y, 0.f);
        }
    }
    __syncthreads();

    if (t < 128) {
        int ri = row0 + t;
        float vb = betab[0], vs = sattb[0], vc = cattb[0];
        float n0 = nodefb[0], n1 = nodefb[1];
        #pragma unroll
        for (int j = 0; j < DH; j++) {
            float e = emb_s[t*33 + j];
            vb += e*betaW[j];
            vs += e*sattW[j];
            vc += e*cattW[j];
            n0 += e*nodefW[j*2+0];
            n1 += e*nodefW[j*2+1];
        }
        g_beta[ri]      = fmaxf(vb, 0.f);
        g_satt[ri]      = fmaxf(vs, 0.f);
        g_catt[ri]      = fmaxf(vc, 0.f);
        g_nodef[ri*2+0] = fmaxf(n0, 0.f);
        g_nodef[ri*2+1] = fmaxf(n1, 0.f);
    }
}

// ---------------- kernel 4: stage-2 gaussians (register coeffs) + softmax ---
__global__ void __launch_bounds__(256) stage2_kernel(
    const float* __restrict__ frame, const int* __restrict__ seq,
    const float* __restrict__ gk2_centers, const float* __restrict__ gk2_prec,
    const float* __restrict__ emb2W, const float* __restrict__ emb2b,
    float* __restrict__ out)
{
    int warp = threadIdx.x >> 5, lane = threadIdx.x & 31;
    int row  = blockIdx.x * 8 + warp;
    int b = row >> 11, l = row & (LSEQ-1);
    const float* fb = frame + (size_t)b * LSEQ * 12;

    int j  = g_idx2[row*K2N + lane];
    int jg = b*LSEQ + j;

    float cix = fb[l*12+0], ciy = fb[l*12+1], ciz = fb[l*12+2];
    float zix = fb[l*12+9], ziy = fb[l*12+10], ziz = fb[l*12+11];
    float cjx = fb[j*12+0], cjy = fb[j*12+1], cjz = fb[j*12+2];
    float zjx = fb[j*12+9], zjy = fb[j*12+10], zjz = fb[j*12+11];
    float dx = cjx-cix, dy = cjy-ciy, dz = cjz-ciz;
    float dist = sqrtf(dx*dx + dy*dy + dz*dz + 1e-12f);
    float zz  = zix*zjx + ziy*zjy + ziz*zjz;
    float ddz = (dx*zjx + dy*zjy + dz*zjz) / dist;
    float zdd = (zix*dx + ziy*dy + ziz*dz) / dist;
    float seqi = (float)seq[b*LSEQ+l];
    float seqj = (float)seq[jg];
    float idist = fminf(fabsf(seqj-seqi), 8.0f);
    float x0 = dist, x1 = zz, x2 = ddz, x3 = zdd, x4 = idist;

    float cen[5], pr[25];
    #pragma unroll
    for (int d = 0; d < 5; d++)  cen[d] = gk2_centers[d*NG + lane];
    #pragma unroll
    for (int i = 0; i < 25; i++) pr[i]  = gk2_prec[i*NG + lane];
    float wn = emb2W[lane];

    float gw_mine = 0.f;
    #pragma unroll 4
    for (int k = 0; k < K2N; k++) {
        float y0 = __shfl_sync(0xffffffffu, x0, k);
        float y1 = __shfl_sync(0xffffffffu, x1, k);
        float y2 = __shfl_sync(0xffffffffu, x2, k);
        float y3 = __shfl_sync(0xffffffffu, x3, k);
        float y4 = __shfl_sync(0xffffffffu, x4, k);
        float d0 = y0-cen[0], d1 = y1-cen[1], d2 = y2-cen[2], d3 = y3-cen[3], d4 = y4-cen[4];
        float s = 0.f;
        #pragma unroll
        for (int c = 0; c < 5; c++) {
            float yv = d0*pr[0*5+c] + d1*pr[1*5+c] + d2*pr[2*5+c]
                     + d3*pr[3*5+c] + d4*pr[4*5+c];
            s += yv*yv;
        }
        float e = __expf(-0.5f*s) * wn;
        #pragma unroll
        for (int off = 16; off > 0; off >>= 1)
            e += __shfl_xor_sync(0xffffffffu, e, off);
        if (lane == k) gw_mine = e;
    }
    float gw = fmaxf(gw_mine + emb2b[0], 0.f);

    float e = (lane == 0) ? g_satt[row] : g_catt[jg];
    float logit = g_beta[row] * e;
    float mx = logit;
    #pragma unroll
    for (int off = 16; off > 0; off >>= 1)
        mx = fmaxf(mx, __shfl_xor_sync(0xffffffffu, mx, off));
    float w = gw * __expf(logit - mx);
    float sw = w;
    #pragma unroll
    for (int off = 16; off > 0; off >>= 1)
        sw += __shfl_xor_sync(0xffffffffu, sw, off);
    float a = w / (sw + 1e-6f);
    float o0 = a * g_nodef[jg*2+0];
    float o1 = a * g_nodef[jg*2+1];
    #pragma unroll
    for (int off = 16; off > 0; off >>= 1) {
        o0 += __shfl_xor_sync(0xffffffffu, o0, off);
        o1 += __shfl_xor_sync(0xffffffffu, o1, off);
    }
    if (lane == 0) { out[row*2+0] = o0; out[row*2+1] = o1; }
}

// ---------------- launcher --------------------------------------------------
extern "C" void kernel_launch(void* const* d_in, const int* in_sizes, int n_in,
                              void* d_out, int out_size)
{
    const float* attr        = (const float*)d_in[0];
    const float* frame       = (const float*)d_in[1];
    const int*   seq         = (const int*)  d_in[2];
    const float* gk1_centers = (const float*)d_in[3];
    const float* gk1_prec    = (const float*)d_in[4];
    const float* opk         = (const float*)d_in[5];
    const float* opb         = (const float*)d_in[6];
    const float* embW        = (const float*)d_in[7];
    const float* embb        = (const float*)d_in[8];
    const float* betaW       = (const float*)d_in[9];
    const float* betab       = (const float*)d_in[10];
    const float* sattW       = (const float*)d_in[11];
    const float* sattb       = (const float*)d_in[12];
    const float* cattW       = (const float*)d_in[13];
    const float* cattb       = (const float*)d_in[14];
    const float* nodefW      = (const float*)d_in[15];
    const float* nodefb      = (const float*)d_in[16];
    const float* gk2_centers = (const float*)d_in[17];
    const float* gk2_prec    = (const float*)d_in[18];
    const float* emb2W       = (const float*)d_in[19];
    const float* emb2b       = (const float*)d_in[20];
    float* out = (float*)d_out;

    cudaFuncSetAttribute(gemm_epi_kernel,
                         cudaFuncAttributeMaxDynamicSharedMemorySize,
                         GE_SMEM_FLOATS * 4);

    pack_kernel<<<NROWS/256, 256>>>(frame);
    bprep_kernel<<<80, 256>>>(opk);
    qprep_kernel<<<1, 32>>>(gk1_centers, gk1_prec);
    knn_kernel<<<NROWS/4, 128>>>();
    stage1_kernel<<<NROWS/8, 256>>>(frame, attr, seq);
    gemm_epi_kernel<<<NROWS/128, 256, GE_SMEM_FLOATS*4>>>(
        opb, embW, embb, betaW, betab,
        sattW, sattb, cattW, cattb, nodefW, nodefb);
    stage2_kernel<<<NROWS/8, 256>>>(frame, seq, gk2_centers, gk2_prec,
                                    emb2W, emb2b, out);
}